// round 14
// baseline (speedup 1.0000x reference)
#include <cuda_runtime.h>

// Problem dims
#define BB 16
#define MM 128
#define NHD 256
#define EHD 128
#define ROWS (BB*MM)     // 2048
#define GRID 512

typedef unsigned long long u64;

// Scratch (static __device__, no allocations)
__device__ __align__(16) float d_aggE[ROWS*EHD];     // Σ_i A*E
__device__ __align__(16) float d_sA[ROWS];           // colsum of A
__device__ __align__(16) float d_Nmap[ROWS*NHD];     // X @ Wv_w
__device__ __align__(16) float d_Hn[ROWS*NHD];       // relu(node)
__device__ __align__(16) float d_He[ROWS*EHD];       // relu(edge)
__device__ __align__(16) float d_partX[ROWS*NHD];    // relu(X)@Wu[384:640]
__device__ __align__(16) float d_partHn[ROWS*NHD];   // Hn@Wu[0:256]

// counters: 0 sa(256) 1 agg(256) 2 nmap(128) 3 hn(128) 4 partx(128)
//           5 parthn(128) 6 he(64) 7 out-queue
__device__ int g_cnt[8];

#define SMEM_FLOATS (2*16*68)

// ---- packed f32x2 helpers ----
__device__ __forceinline__ u64 bcast2(float v) {
    u64 r; asm("mov.b64 %0, {%1, %1};" : "=l"(r) : "f"(v)); return r;
}
__device__ __forceinline__ void fmax2(u64 &d, u64 a, u64 b) {
    asm("fma.rn.f32x2 %0, %1, %2, %0;" : "+l"(d) : "l"(a), "l"(b));
}
__device__ __forceinline__ void unpack2(u64 v, float &lo, float &hi) {
    asm("mov.b64 {%0, %1}, %2;" : "=f"(lo), "=f"(hi) : "l"(v));
}

// ---- flag signal / wait ----
__device__ __forceinline__ void signal(int idx) {
    __syncthreads();
    if (threadIdx.x == 0) { __threadfence(); atomicAdd(&g_cnt[idx], 1); }
}
__device__ __forceinline__ void waitfor(int idx, int target) {
    if (threadIdx.x == 0) {
        while (*(volatile int*)&g_cnt[idx] < target) __nanosleep(128);
        __threadfence();
    }
    __syncthreads();
}

// ---------------------------------------------------------------------------
// 256-thread GEMM: 64x64 tile, BK=16, 4x4 f32x2 micro-tile, reg prefetch.
//   TRANSA: A is [k][m];  RELUA: relu on A load;  EPI: relu(acc+srow*bias)
// ---------------------------------------------------------------------------
template<bool TRANSA, bool RELUA, bool EPI>
__device__ __forceinline__
void devgemm(const float* __restrict__ Ab, int lda,
             const float* __restrict__ Bb, int ldb,
             float* __restrict__ Cb, int ldc, int K,
             const float* __restrict__ bias,
             const float* __restrict__ srow,
             int m0, int n0, float* sm) {
    float (*As)[68] = (float(*)[68])sm;
    float (*Bs)[68] = (float(*)[68])(sm + 16*68);

    const int tid = threadIdx.x;
    const int tx = tid & 15;
    const int ty = tid >> 4;

    u64 acc2[4][2] = {};

    float4 ra, rb;
    {
        if (TRANSA) {
            int kk = tid >> 4, c4 = tid & 15;
            ra = *(const float4*)&Ab[(long)kk * lda + m0 + c4 * 4];
        } else {
            int r = tid >> 2, c4 = tid & 3;
            ra = *(const float4*)&Ab[(long)(m0 + r) * lda + c4 * 4];
        }
        int kk = tid >> 4, c4 = tid & 15;
        rb = *(const float4*)&Bb[(long)kk * ldb + n0 + c4 * 4];
    }

    for (int k0 = 0; k0 < K; k0 += 16) {
        if (RELUA) {
            ra.x = fmaxf(ra.x, 0.f); ra.y = fmaxf(ra.y, 0.f);
            ra.z = fmaxf(ra.z, 0.f); ra.w = fmaxf(ra.w, 0.f);
        }
        if (TRANSA) {
            int kk = tid >> 4, c4 = tid & 15;
            *(float4*)&As[kk][c4 * 4] = ra;
        } else {
            int r = tid >> 2, c4 = tid & 3;
            As[c4 * 4 + 0][r] = ra.x;
            As[c4 * 4 + 1][r] = ra.y;
            As[c4 * 4 + 2][r] = ra.z;
            As[c4 * 4 + 3][r] = ra.w;
        }
        {
            int kk = tid >> 4, c4 = tid & 15;
            *(float4*)&Bs[kk][c4 * 4] = rb;
        }
        __syncthreads();

        int kn = k0 + 16;
        if (kn < K) {
            if (TRANSA) {
                int kk = tid >> 4, c4 = tid & 15;
                ra = *(const float4*)&Ab[(long)(kn + kk) * lda + m0 + c4 * 4];
            } else {
                int r = tid >> 2, c4 = tid & 3;
                ra = *(const float4*)&Ab[(long)(m0 + r) * lda + kn + c4 * 4];
            }
            int kk = tid >> 4, c4 = tid & 15;
            rb = *(const float4*)&Bb[(long)(kn + kk) * ldb + n0 + c4 * 4];
        }

        #pragma unroll
        for (int k = 0; k < 16; k++) {
            float4 a4 = *(const float4*)&As[k][ty * 4];
            ulonglong2 bv = *(const ulonglong2*)&Bs[k][tx * 4];
            u64 a0 = bcast2(a4.x), a1 = bcast2(a4.y);
            u64 a2 = bcast2(a4.z), a3 = bcast2(a4.w);
            fmax2(acc2[0][0], a0, bv.x); fmax2(acc2[0][1], a0, bv.y);
            fmax2(acc2[1][0], a1, bv.x); fmax2(acc2[1][1], a1, bv.y);
            fmax2(acc2[2][0], a2, bv.x); fmax2(acc2[2][1], a2, bv.y);
            fmax2(acc2[3][0], a3, bv.x); fmax2(acc2[3][1], a3, bv.y);
        }
        __syncthreads();
    }

    float4 bvv = make_float4(0.f, 0.f, 0.f, 0.f);
    if (EPI) bvv = *(const float4*)&bias[n0 + tx * 4];

    #pragma unroll
    for (int mm = 0; mm < 4; mm++) {
        int r = m0 + ty * 4 + mm;
        float4 v;
        unpack2(acc2[mm][0], v.x, v.y);
        unpack2(acc2[mm][1], v.z, v.w);
        if (EPI) {
            float s = srow[r];
            v.x = fmaxf(fmaf(s, bvv.x, v.x), 0.f);
            v.y = fmaxf(fmaf(s, bvv.y, v.y), 0.f);
            v.z = fmaxf(fmaf(s, bvv.z, v.z), 0.f);
            v.w = fmaxf(fmaf(s, bvv.w, v.w), 0.f);
        }
        *(float4*)&Cb[(long)r * ldc + n0 + tx * 4] = v;
    }
}

// ---------------------------------------------------------------------------
// out final: K=128 over He, + partHn + partX + bias, * w
// ---------------------------------------------------------------------------
__device__ __forceinline__
void out_final(const float* __restrict__ Wu_w, const float* __restrict__ Wu_b,
               const float* __restrict__ w, float* __restrict__ out,
               int m0, int n0, float* sm) {
    float (*As)[68] = (float(*)[68])sm;
    float (*Bs)[68] = (float(*)[68])(sm + 16*68);
    const float* Bb = Wu_w + (long)NHD * NHD;   // rows 256:384

    const int tid = threadIdx.x;
    const int tx = tid & 15;
    const int ty = tid >> 4;

    u64 acc2[4][2] = {};

    float4 ra, rb;
    {
        int r = tid >> 2, c4 = tid & 3;
        ra = *(const float4*)&d_He[(long)(m0 + r) * EHD + c4 * 4];
        int kk = tid >> 4, c4b = tid & 15;
        rb = *(const float4*)&Bb[(long)kk * NHD + n0 + c4b * 4];
    }

    for (int k0 = 0; k0 < EHD; k0 += 16) {
        {
            int r = tid >> 2, c4 = tid & 3;
            As[c4 * 4 + 0][r] = ra.x;
            As[c4 * 4 + 1][r] = ra.y;
            As[c4 * 4 + 2][r] = ra.z;
            As[c4 * 4 + 3][r] = ra.w;
            int kk = tid >> 4, c4b = tid & 15;
            *(float4*)&Bs[kk][c4b * 4] = rb;
        }
        __syncthreads();

        int kn = k0 + 16;
        if (kn < EHD) {
            int r = tid >> 2, c4 = tid & 3;
            ra = *(const float4*)&d_He[(long)(m0 + r) * EHD + kn + c4 * 4];
            int kk = tid >> 4, c4b = tid & 15;
            rb = *(const float4*)&Bb[(long)(kn + kk) * NHD + n0 + c4b * 4];
        }

        #pragma unroll
        for (int k = 0; k < 16; k++) {
            float4 a4 = *(const float4*)&As[k][ty * 4];
            ulonglong2 bv = *(const ulonglong2*)&Bs[k][tx * 4];
            u64 a0 = bcast2(a4.x), a1 = bcast2(a4.y);
            u64 a2 = bcast2(a4.z), a3 = bcast2(a4.w);
            fmax2(acc2[0][0], a0, bv.x); fmax2(acc2[0][1], a0, bv.y);
            fmax2(acc2[1][0], a1, bv.x); fmax2(acc2[1][1], a1, bv.y);
            fmax2(acc2[2][0], a2, bv.x); fmax2(acc2[2][1], a2, bv.y);
            fmax2(acc2[3][0], a3, bv.x); fmax2(acc2[3][1], a3, bv.y);
        }
        __syncthreads();
    }

    float4 bvv = *(const float4*)&Wu_b[n0 + tx * 4];
    #pragma unroll
    for (int mm = 0; mm < 4; mm++) {
        int r = m0 + ty * 4 + mm;
        float4 p1 = *(const float4*)&d_partHn[(long)r * NHD + n0 + tx * 4];
        float4 p2 = *(const float4*)&d_partX[(long)r * NHD + n0 + tx * 4];
        float wv = w[r];
        float4 v;
        unpack2(acc2[mm][0], v.x, v.y);
        unpack2(acc2[mm][1], v.z, v.w);
        v.x = (v.x + p1.x + p2.x + bvv.x) * wv;
        v.y = (v.y + p1.y + p2.y + bvv.y) * wv;
        v.z = (v.z + p1.z + p2.z + bvv.z) * wv;
        v.w = (v.w + p1.w + p2.w + bvv.w) * wv;
        *(float4*)&out[(long)r * NHD + n0 + tx * 4] = v;
    }
}

// ---------------------------------------------------------------------------
// ereduce8: 8 j's per block; writes sA (signal 0) then aggE (signal 1).
// ---------------------------------------------------------------------------
__device__ __forceinline__
void ereduce8(const float* __restrict__ E, const float* __restrict__ A,
              int b, int jg, float* sm) {
    float (*As8)[MM] = (float(*)[MM])sm;
    const int tid = threadIdx.x;
    const int jl  = tid >> 5;
    const int lane = tid & 31;
    const int j0 = jg * 8;

    const float* Ab = A + (long)b * MM * MM;
    for (int idx = tid; idx < 8 * MM; idx += 256) {
        int jj = idx & 7;
        int i  = idx >> 3;
        As8[jj][i] = Ab[i * MM + j0 + jj];
    }
    __syncthreads();

    if (tid < 8) {
        float s = 0.f;
        #pragma unroll
        for (int i = 0; i < MM; i++) s += As8[tid][i];
        d_sA[b * MM + j0 + tid] = s;
    }
    signal(0);   // sA chunk published

    const int j = j0 + jl;
    const float4* Ep = (const float4*)E + ((long)(b * MM) * MM + j) * (EHD / 4) + lane;
    const long istride = (long)MM * (EHD / 4);

    float4 acc = make_float4(0.f, 0.f, 0.f, 0.f);
    #pragma unroll 8
    for (int i = 0; i < MM; i++) {
        float a  = As8[jl][i];
        float4 v = Ep[(long)i * istride];
        acc.x = fmaf(a, v.x, acc.x);
        acc.y = fmaf(a, v.y, acc.y);
        acc.z = fmaf(a, v.z, acc.z);
        acc.w = fmaf(a, v.w, acc.w);
    }
    ((float4*)d_aggE)[(long)(b * MM + j) * (EHD / 4) + lane] = acc;
    signal(1);   // aggE chunk published
}

// ---------------------------------------------------------------------------
__global__ void reset_kernel() {
    if (threadIdx.x < 8) g_cnt[threadIdx.x] = 0;
}

// ---------------------------------------------------------------------------
// Dataflow mega kernel.
// ---------------------------------------------------------------------------
__global__ __launch_bounds__(256, 4)
void mega_kernel(const float* __restrict__ E, const float* __restrict__ A,
                 const float* __restrict__ X,
                 const float* __restrict__ Wv_w, const float* __restrict__ Wv_b,
                 const float* __restrict__ We_w, const float* __restrict__ We_b,
                 const float* __restrict__ Wu_w, const float* __restrict__ Wu_b,
                 const float* __restrict__ w, float* __restrict__ out) {
    __shared__ __align__(16) float sm[SMEM_FLOATS];
    __shared__ int s_ticket;
    const int blk = blockIdx.x;

    if (blk < 256) {
        // Lane S: E stream
        ereduce8(E, A, blk >> 4, blk & 15, sm);
    } else if (blk < 384) {
        // Lane A: Nmap -> Hn -> (first 64) He
        int t = blk - 256;
        {
            int mt = t >> 2, nt = t & 3;
            devgemm<false, false, false>(
                X, NHD, Wv_w, NHD, d_Nmap, NHD,
                NHD, nullptr, nullptr, mt * 64, nt * 64, sm);
        }
        signal(2);
        waitfor(2, 128);
        waitfor(0, 256);
        {
            // Hn[b] tile: K=128, A^T form
            int b = t >> 3, tt = t & 7;
            int mt = tt >> 2, nt = tt & 3;
            devgemm<true, false, true>(
                A + (long)b * MM * MM, MM,
                d_Nmap + (long)b * MM * NHD, NHD,
                d_Hn + (long)b * MM * NHD, NHD,
                MM, Wv_b, d_sA + b * MM, mt * 64, nt * 64, sm);
        }
        signal(3);
        if (t < 64) {
            waitfor(1, 256);
            int mt = t >> 1, nt = t & 1;
            devgemm<false, false, true>(
                d_aggE, EHD, We_w, EHD, d_He, EHD,
                EHD, We_b, d_sA, mt * 64, nt * 64, sm);
            signal(6);
        }
    } else {
        // Lane B: partX -> partHn
        int t = blk - 384;
        {
            int mt = t >> 2, nt = t & 3;
            devgemm<false, true, false>(
                X, NHD, Wu_w + (long)384 * NHD, NHD, d_partX, NHD,
                NHD, nullptr, nullptr, mt * 64, nt * 64, sm);
        }
        signal(4);
        waitfor(3, 128);
        {
            int mt = t >> 2, nt = t & 3;
            devgemm<false, false, false>(
                d_Hn, NHD, Wu_w, NHD, d_partHn, NHD,
                NHD, nullptr, nullptr, mt * 64, nt * 64, sm);
        }
        signal(5);
    }

    // out queue: 128 tiles
    if (threadIdx.x == 0) s_ticket = atomicAdd(&g_cnt[7], 1);
    __syncthreads();
    int tk = s_ticket;
    if (tk < 128) {
        waitfor(6, 64);
        waitfor(5, 128);
        waitfor(4, 128);
        int mt = tk >> 2, nt = tk & 3;
        out_final(Wu_w, Wu_b, w, out, mt * 64, nt * 64, sm);
    }
}

// ---------------------------------------------------------------------------
extern "C" void kernel_launch(void* const* d_in, const int* in_sizes, int n_in,
                              void* d_out, int out_size) {
    const float* X    = (const float*)d_in[0];   // [16,128,256]
    const float* E    = (const float*)d_in[1];   // [16,128,128,128]
    const float* A    = (const float*)d_in[2];   // [16,128,128]
    const float* w    = (const float*)d_in[3];   // [16,128,1]
    const float* Wv_w = (const float*)d_in[4];   // [256,256]
    const float* Wv_b = (const float*)d_in[5];   // [256]
    const float* We_w = (const float*)d_in[6];   // [128,128]
    const float* We_b = (const float*)d_in[7];   // [128]
    const float* Wu_w = (const float*)d_in[8];   // [640,256]
    const float* Wu_b = (const float*)d_in[9];   // [256]
    float* out = (float*)d_out;                  // [16,128,256]

    reset_kernel<<<1, 32>>>();
    mega_kernel<<<GRID, 256>>>(E, A, X, Wv_w, Wv_b, We_w, We_b,
                               Wu_w, Wu_b, w, out);
}

// round 16
// speedup vs baseline: 1.0376x; 1.0376x over previous
#include <cuda_runtime.h>

// Problem dims
#define BB 16
#define MM 128
#define NHD 256
#define EHD 128
#define ROWS (BB*MM)     // 2048

typedef unsigned long long u64;

// Scratch (static __device__, no allocations)
__device__ __align__(16) float d_aggE[ROWS*EHD];     // Σ_i A*E
__device__ __align__(16) float d_sA[ROWS];           // colsum of A
__device__ __align__(16) float d_Nmap[ROWS*NHD];     // X @ Wv_w
__device__ __align__(16) float d_Hn[ROWS*NHD];       // relu(node)
__device__ __align__(16) float d_He[ROWS*EHD];       // relu(edge)
__device__ __align__(16) float d_partX[ROWS*NHD];    // relu(X)@Wu[384:640]
__device__ __align__(16) float d_partHn[ROWS*NHD];   // Hn@Wu[0:256]

#define SMEM_FLOATS (2*16*68)

// ---- packed f32x2 helpers ----
__device__ __forceinline__ u64 bcast2(float v) {
    u64 r; asm("mov.b64 %0, {%1, %1};" : "=l"(r) : "f"(v)); return r;
}
__device__ __forceinline__ void fmax2(u64 &d, u64 a, u64 b) {
    asm("fma.rn.f32x2 %0, %1, %2, %0;" : "+l"(d) : "l"(a), "l"(b));
}
__device__ __forceinline__ void unpack2(u64 v, float &lo, float &hi) {
    asm("mov.b64 {%0, %1}, %2;" : "=f"(lo), "=f"(hi) : "l"(v));
}

// ---------------------------------------------------------------------------
// 256-thread GEMM: 64x64 tile, BK=16, 4x4 f32x2 micro-tile, reg prefetch.
//   TRANSA: A is [k][m];  RELUA: relu on A load;  EPI: relu(acc+srow*bias)
// ---------------------------------------------------------------------------
template<bool TRANSA, bool RELUA, bool EPI>
__device__ __forceinline__
void devgemm(const float* __restrict__ Ab, int lda,
             const float* __restrict__ Bb, int ldb,
             float* __restrict__ Cb, int ldc, int K,
             const float* __restrict__ bias,
             const float* __restrict__ srow,
             int m0, int n0, float* sm) {
    float (*As)[68] = (float(*)[68])sm;
    float (*Bs)[68] = (float(*)[68])(sm + 16*68);

    const int tid = threadIdx.x;
    const int tx = tid & 15;
    const int ty = tid >> 4;

    u64 acc2[4][2] = {};

    float4 ra, rb;
    {
        if (TRANSA) {
            int kk = tid >> 4, c4 = tid & 15;
            ra = *(const float4*)&Ab[(long)kk * lda + m0 + c4 * 4];
        } else {
            int r = tid >> 2, c4 = tid & 3;
            ra = *(const float4*)&Ab[(long)(m0 + r) * lda + c4 * 4];
        }
        int kk = tid >> 4, c4 = tid & 15;
        rb = *(const float4*)&Bb[(long)kk * ldb + n0 + c4 * 4];
    }

    for (int k0 = 0; k0 < K; k0 += 16) {
        if (RELUA) {
            ra.x = fmaxf(ra.x, 0.f); ra.y = fmaxf(ra.y, 0.f);
            ra.z = fmaxf(ra.z, 0.f); ra.w = fmaxf(ra.w, 0.f);
        }
        if (TRANSA) {
            int kk = tid >> 4, c4 = tid & 15;
            *(float4*)&As[kk][c4 * 4] = ra;
        } else {
            int r = tid >> 2, c4 = tid & 3;
            As[c4 * 4 + 0][r] = ra.x;
            As[c4 * 4 + 1][r] = ra.y;
            As[c4 * 4 + 2][r] = ra.z;
            As[c4 * 4 + 3][r] = ra.w;
        }
        {
            int kk = tid >> 4, c4 = tid & 15;
            *(float4*)&Bs[kk][c4 * 4] = rb;
        }
        __syncthreads();

        int kn = k0 + 16;
        if (kn < K) {
            if (TRANSA) {
                int kk = tid >> 4, c4 = tid & 15;
                ra = *(const float4*)&Ab[(long)(kn + kk) * lda + m0 + c4 * 4];
            } else {
                int r = tid >> 2, c4 = tid & 3;
                ra = *(const float4*)&Ab[(long)(m0 + r) * lda + kn + c4 * 4];
            }
            int kk = tid >> 4, c4 = tid & 15;
            rb = *(const float4*)&Bb[(long)(kn + kk) * ldb + n0 + c4 * 4];
        }

        #pragma unroll
        for (int k = 0; k < 16; k++) {
            float4 a4 = *(const float4*)&As[k][ty * 4];
            ulonglong2 bv = *(const ulonglong2*)&Bs[k][tx * 4];
            u64 a0 = bcast2(a4.x), a1 = bcast2(a4.y);
            u64 a2 = bcast2(a4.z), a3 = bcast2(a4.w);
            fmax2(acc2[0][0], a0, bv.x); fmax2(acc2[0][1], a0, bv.y);
            fmax2(acc2[1][0], a1, bv.x); fmax2(acc2[1][1], a1, bv.y);
            fmax2(acc2[2][0], a2, bv.x); fmax2(acc2[2][1], a2, bv.y);
            fmax2(acc2[3][0], a3, bv.x); fmax2(acc2[3][1], a3, bv.y);
        }
        __syncthreads();
    }

    float4 bvv = make_float4(0.f, 0.f, 0.f, 0.f);
    if (EPI) bvv = *(const float4*)&bias[n0 + tx * 4];

    #pragma unroll
    for (int mm = 0; mm < 4; mm++) {
        int r = m0 + ty * 4 + mm;
        float4 v;
        unpack2(acc2[mm][0], v.x, v.y);
        unpack2(acc2[mm][1], v.z, v.w);
        if (EPI) {
            float s = srow[r];
            v.x = fmaxf(fmaf(s, bvv.x, v.x), 0.f);
            v.y = fmaxf(fmaf(s, bvv.y, v.y), 0.f);
            v.z = fmaxf(fmaf(s, bvv.z, v.z), 0.f);
            v.w = fmaxf(fmaf(s, bvv.w, v.w), 0.f);
        }
        *(float4*)&Cb[(long)r * ldc + n0 + tx * 4] = v;
    }
}

// ---------------------------------------------------------------------------
// out final: K=128 over He, + partHn + partX + bias, * w
// ---------------------------------------------------------------------------
__device__ __forceinline__
void out_final(const float* __restrict__ Wu_w, const float* __restrict__ Wu_b,
               const float* __restrict__ w, float* __restrict__ out,
               int m0, int n0, float* sm) {
    float (*As)[68] = (float(*)[68])sm;
    float (*Bs)[68] = (float(*)[68])(sm + 16*68);
    const float* Bb = Wu_w + (long)NHD * NHD;   // rows 256:384

    const int tid = threadIdx.x;
    const int tx = tid & 15;
    const int ty = tid >> 4;

    u64 acc2[4][2] = {};

    float4 ra, rb;
    {
        int r = tid >> 2, c4 = tid & 3;
        ra = *(const float4*)&d_He[(long)(m0 + r) * EHD + c4 * 4];
        int kk = tid >> 4, c4b = tid & 15;
        rb = *(const float4*)&Bb[(long)kk * NHD + n0 + c4b * 4];
    }

    for (int k0 = 0; k0 < EHD; k0 += 16) {
        {
            int r = tid >> 2, c4 = tid & 3;
            As[c4 * 4 + 0][r] = ra.x;
            As[c4 * 4 + 1][r] = ra.y;
            As[c4 * 4 + 2][r] = ra.z;
            As[c4 * 4 + 3][r] = ra.w;
            int kk = tid >> 4, c4b = tid & 15;
            *(float4*)&Bs[kk][c4b * 4] = rb;
        }
        __syncthreads();

        int kn = k0 + 16;
        if (kn < EHD) {
            int r = tid >> 2, c4 = tid & 3;
            ra = *(const float4*)&d_He[(long)(m0 + r) * EHD + kn + c4 * 4];
            int kk = tid >> 4, c4b = tid & 15;
            rb = *(const float4*)&Bb[(long)(kn + kk) * NHD + n0 + c4b * 4];
        }

        #pragma unroll
        for (int k = 0; k < 16; k++) {
            float4 a4 = *(const float4*)&As[k][ty * 4];
            ulonglong2 bv = *(const ulonglong2*)&Bs[k][tx * 4];
            u64 a0 = bcast2(a4.x), a1 = bcast2(a4.y);
            u64 a2 = bcast2(a4.z), a3 = bcast2(a4.w);
            fmax2(acc2[0][0], a0, bv.x); fmax2(acc2[0][1], a0, bv.y);
            fmax2(acc2[1][0], a1, bv.x); fmax2(acc2[1][1], a1, bv.y);
            fmax2(acc2[2][0], a2, bv.x); fmax2(acc2[2][1], a2, bv.y);
            fmax2(acc2[3][0], a3, bv.x); fmax2(acc2[3][1], a3, bv.y);
        }
        __syncthreads();
    }

    float4 bvv = *(const float4*)&Wu_b[n0 + tx * 4];
    #pragma unroll
    for (int mm = 0; mm < 4; mm++) {
        int r = m0 + ty * 4 + mm;
        float4 p1 = *(const float4*)&d_partHn[(long)r * NHD + n0 + tx * 4];
        float4 p2 = *(const float4*)&d_partX[(long)r * NHD + n0 + tx * 4];
        float wv = w[r];
        float4 v;
        unpack2(acc2[mm][0], v.x, v.y);
        unpack2(acc2[mm][1], v.z, v.w);
        v.x = (v.x + p1.x + p2.x + bvv.x) * wv;
        v.y = (v.y + p1.y + p2.y + bvv.y) * wv;
        v.z = (v.z + p1.z + p2.z + bvv.z) * wv;
        v.w = (v.w + p1.w + p2.w + bvv.w) * wv;
        *(float4*)&out[(long)r * NHD + n0 + tx * 4] = v;
    }
}

// ---------------------------------------------------------------------------
// ereduce8: 8 j's per block, one warp each (no sA — precomputed in L0).
// ---------------------------------------------------------------------------
__device__ __forceinline__
void ereduce8(const float* __restrict__ E, const float* __restrict__ A,
              int b, int jg, float* sm) {
    float (*As8)[MM] = (float(*)[MM])sm;
    const int tid = threadIdx.x;
    const int jl  = tid >> 5;
    const int lane = tid & 31;
    const int j0 = jg * 8;

    const float* Ab = A + (long)b * MM * MM;
    for (int idx = tid; idx < 8 * MM; idx += 256) {
        int jj = idx & 7;
        int i  = idx >> 3;
        As8[jj][i] = Ab[i * MM + j0 + jj];
    }
    __syncthreads();

    const int j = j0 + jl;
    const float4* Ep = (const float4*)E + ((long)(b * MM) * MM + j) * (EHD / 4) + lane;
    const long istride = (long)MM * (EHD / 4);

    float4 acc = make_float4(0.f, 0.f, 0.f, 0.f);
    #pragma unroll 8
    for (int i = 0; i < MM; i++) {
        float a  = As8[jl][i];
        float4 v = Ep[(long)i * istride];
        acc.x = fmaf(a, v.x, acc.x);
        acc.y = fmaf(a, v.y, acc.y);
        acc.z = fmaf(a, v.z, acc.z);
        acc.w = fmaf(a, v.w, acc.w);
    }
    ((float4*)d_aggE)[(long)(b * MM + j) * (EHD / 4) + lane] = acc;
}

// ---------------------------------------------------------------------------
// L0 (272 blocks): Nmap [0,128) | partX [128,256) | sA [256,272)
// ---------------------------------------------------------------------------
__global__ __launch_bounds__(256, 4)
void l0_kernel(const float* __restrict__ X, const float* __restrict__ A,
               const float* __restrict__ Wv_w, const float* __restrict__ Wu_w) {
    __shared__ __align__(16) float sm[SMEM_FLOATS];
    const int blk = blockIdx.x;

    if (blk < 128) {
        // Nmap = X @ Wv_w  (raw)
        int mt = blk >> 2, nt = blk & 3;
        devgemm<false, false, false>(
            X, NHD, Wv_w, NHD, d_Nmap, NHD,
            NHD, nullptr, nullptr, mt * 64, nt * 64, sm);
    } else if (blk < 256) {
        // partX = relu(X) @ Wu_w[384:640]
        int idx = blk - 128;
        int mt = idx >> 2, nt = idx & 3;
        devgemm<false, true, false>(
            X, NHD, Wu_w + (long)384 * NHD, NHD, d_partX, NHD,
            NHD, nullptr, nullptr, mt * 64, nt * 64, sm);
    } else {
        // sA[b, :] = colsum of A[b]
        int b = blk - 256;
        int t = threadIdx.x;
        if (t < MM) {
            const float* Ab = A + (long)b * MM * MM;
            float s = 0.f;
            #pragma unroll 8
            for (int i = 0; i < MM; i++) s += Ab[i * MM + t];
            d_sA[b * MM + t] = s;
        }
    }
}

// ---------------------------------------------------------------------------
// L1 (384 blocks): E-stream [0,256) | Hn [256,384)  (Hn hides under stream)
// ---------------------------------------------------------------------------
__global__ __launch_bounds__(256, 4)
void l1_kernel(const float* __restrict__ E, const float* __restrict__ A,
               const float* __restrict__ Wv_b) {
    __shared__ __align__(16) float sm[SMEM_FLOATS];
    const int blk = blockIdx.x;

    if (blk < 256) {
        ereduce8(E, A, blk >> 4, blk & 15, sm);
    } else {
        // Hn[b] = relu(A[b]^T @ Nmap[b] + sA*Wv_b)   (K=128)
        int t = blk - 256;
        int b = t >> 3, tt = t & 7;
        int mt = tt >> 2, nt = tt & 3;
        devgemm<true, false, true>(
            A + (long)b * MM * MM, MM,
            d_Nmap + (long)b * MM * NHD, NHD,
            d_Hn + (long)b * MM * NHD, NHD,
            MM, Wv_b, d_sA + b * MM, mt * 64, nt * 64, sm);
    }
}

// ---------------------------------------------------------------------------
// L2 (192 blocks): He [0,64) | partHn [64,192)  (independent)
// ---------------------------------------------------------------------------
__global__ __launch_bounds__(256, 4)
void l2_kernel(const float* __restrict__ We_w, const float* __restrict__ We_b,
               const float* __restrict__ Wu_w) {
    __shared__ __align__(16) float sm[SMEM_FLOATS];
    const int blk = blockIdx.x;

    if (blk < 64) {
        // He = relu(aggE @ We_w + sA*We_b)   (K=128)
        int mt = blk >> 1, nt = blk & 1;
        devgemm<false, false, true>(
            d_aggE, EHD, We_w, EHD, d_He, EHD,
            EHD, We_b, d_sA, mt * 64, nt * 64, sm);
    } else {
        // partHn = Hn @ Wu_w[0:256]   (K=256, raw)
        int idx = blk - 64;
        int mt = idx >> 2, nt = idx & 3;
        devgemm<false, false, false>(
            d_Hn, NHD, Wu_w, NHD, d_partHn, NHD,
            NHD, nullptr, nullptr, mt * 64, nt * 64, sm);
    }
}

// ---------------------------------------------------------------------------
// L3 (128 blocks): out = (He@Wu[256:384] + partHn + partX + Wu_b) * w
// ---------------------------------------------------------------------------
__global__ __launch_bounds__(256, 4)
void l3_kernel(const float* __restrict__ Wu_w, const float* __restrict__ Wu_b,
               const float* __restrict__ w, float* __restrict__ out) {
    __shared__ __align__(16) float sm[SMEM_FLOATS];
    const int blk = blockIdx.x;
    int mt = blk >> 2, nt = blk & 3;
    out_final(Wu_w, Wu_b, w, out, mt * 64, nt * 64, sm);
}

// ---------------------------------------------------------------------------
extern "C" void kernel_launch(void* const* d_in, const int* in_sizes, int n_in,
                              void* d_out, int out_size) {
    const float* X    = (const float*)d_in[0];   // [16,128,256]
    const float* E    = (const float*)d_in[1];   // [16,128,128,128]
    const float* A    = (const float*)d_in[2];   // [16,128,128]
    const float* w    = (const float*)d_in[3];   // [16,128,1]
    const float* Wv_w = (const float*)d_in[4];   // [256,256]
    const float* Wv_b = (const float*)d_in[5];   // [256]
    const float* We_w = (const float*)d_in[6];   // [128,128]
    const float* We_b = (const float*)d_in[7];   // [128]
    const float* Wu_w = (const float*)d_in[8];   // [640,256]
    const float* Wu_b = (const float*)d_in[9];   // [256]
    float* out = (float*)d_out;                  // [16,128,256]

    // L0: Nmap | partX | sA (all dependency-free)
    l0_kernel<<<272, 256>>>(X, A, Wv_w, Wu_w);

    // L1: E-stream | Hn (hides under the 134MB HBM stream)
    l1_kernel<<<384, 256>>>(E, A, Wv_b);

    // L2: He | partHn (independent halves of the output GEMM prep)
    l2_kernel<<<192, 256>>>(We_w, We_b, Wu_w);

    // L3: final combine (K=128 GEMM + adds + scale)
    l3_kernel<<<128, 256>>>(Wu_w, Wu_b, w, out);
}